// round 2
// baseline (speedup 1.0000x reference)
#include <cuda_runtime.h>
#include <cstdint>

// ---------------------------------------------------------------------------
// 2-layer LSTM, B=64, S=512, I=64, H=512, fc head on final h1.
// Persistent kernel, 128 CTAs (64 per layer) x 256 threads.
// Phase p: layer0 computes step t=p (p<512), layer1 computes step t=p-1.
// Weights resident in SMEM (tf32). GEMM via mma.sync m16n8k8 tf32.
// 8 warps/CTA: warp-group 0 (warps 0-3) does K-half 0, wg1 does K-half 1,
// reduced through SMEM. Cell state c lives in registers. Decentralized
// flag-array grid barrier with monotone generation counters.
// ---------------------------------------------------------------------------

#define NC    128
#define NTHR  256
#define BSZ   64
#define HID   512
#define INP   64
#define SEQ   512
#define K0    576
#define K1    1024
#define NK8_0 (K0/8)    // 72
#define NK8_1 (K1/8)    // 128
#define SMEM_W_FLOATS (1024*32)
#define SMEM_RED_FLOATS (4*32*16)
#define SMEM_BYTES ((SMEM_W_FLOATS + SMEM_RED_FLOATS + 32)*4)

// persistent state (device globals: no allocation allowed)
__device__ float g_xT[SEQ*INP*BSZ];      // [t][i][b], tf32-rounded
__device__ float g_h0T[2][HID*BSZ];      // ping-pong [n][b]
__device__ float g_h1T[2][HID*BSZ];
__device__ unsigned g_flags[NC*8];       // 32B-strided, monotone across replays

__device__ __forceinline__ unsigned f2tf32(float f) {
    unsigned r;
    asm("cvt.rna.tf32.f32 %0, %1;" : "=r"(r) : "f"(f));
    return r;
}

__device__ __forceinline__ void mma8(float (&d)[4],
                                     unsigned a0, unsigned a1, unsigned a2, unsigned a3,
                                     float b0, float b1) {
    asm volatile(
        "mma.sync.aligned.m16n8k8.row.col.f32.tf32.tf32.f32 "
        "{%0,%1,%2,%3}, {%4,%5,%6,%7}, {%8,%9}, {%0,%1,%2,%3};"
        : "+f"(d[0]), "+f"(d[1]), "+f"(d[2]), "+f"(d[3])
        : "r"(a0), "r"(a1), "r"(a2), "r"(a3),
          "r"(__float_as_uint(b0)), "r"(__float_as_uint(b1)));
}

__device__ __forceinline__ float fast_tanh(float x) {
    float r;
    asm("tanh.approx.f32 %0, %1;" : "=f"(r) : "f"(x));
    return r;
}
__device__ __forceinline__ float sigm(float x) {
    return 0.5f * fast_tanh(0.5f * x) + 0.5f;
}

// --- decentralized grid barrier ------------------------------------------
// Each CTA publishes flags[cta] = epoch + gen (release). Threads t<NC each
// poll one flag. Monotone counters survive graph replays (epoch read at start).
__device__ __forceinline__ void grid_bar(int cta, int tid, unsigned epoch, unsigned gen) {
    __syncthreads();
    if (tid == 0) {
        __threadfence();
        *(volatile unsigned*)&g_flags[cta * 8] = epoch + gen;
    }
    if (tid < NC) {
        const unsigned target = epoch + gen;
        volatile unsigned* f = &g_flags[tid * 8];
        while ((int)(*f - target) < 0) __nanosleep(32);
    }
    __threadfence();
    __syncthreads();
}

// --- K-range GEMM: A from L2 (prefetched), B (weights) from SMEM ----------
__device__ __forceinline__ void gemm_range(float (&acc)[4][4],
                                           const float* __restrict__ aA,
                                           const float* __restrict__ aB,
                                           int split, int k8b, int k8e,
                                           const float* __restrict__ sW,
                                           int aoff, int boff) {
    const float* ab = (k8b < split) ? aA + k8b * 512 : aB + (k8b - split) * 512;
    unsigned p0 = __float_as_uint(__ldcg(ab + aoff));
    unsigned p1 = __float_as_uint(__ldcg(ab + aoff + 8));
    unsigned p2 = __float_as_uint(__ldcg(ab + aoff + 256));
    unsigned p3 = __float_as_uint(__ldcg(ab + aoff + 264));
#pragma unroll 4
    for (int k8 = k8b; k8 < k8e; ++k8) {
        unsigned a0 = p0, a1 = p1, a2 = p2, a3 = p3;
        int kn = k8 + 1;
        if (kn < k8e) {
            const float* abn = (kn < split) ? aA + kn * 512 : aB + (kn - split) * 512;
            p0 = __float_as_uint(__ldcg(abn + aoff));
            p1 = __float_as_uint(__ldcg(abn + aoff + 8));
            p2 = __float_as_uint(__ldcg(abn + aoff + 256));
            p3 = __float_as_uint(__ldcg(abn + aoff + 264));
        }
        const float* bp = sW + k8 * 256 + boff;
        float4 bl = *(const float4*)bp;
        float4 bh = *(const float4*)(bp + 128);
        mma8(acc[0], a0, a1, a2, a3, bl.x, bh.x);
        mma8(acc[1], a0, a1, a2, a3, bl.y, bh.y);
        mma8(acc[2], a0, a1, a2, a3, bl.z, bh.z);
        mma8(acc[3], a0, a1, a2, a3, bl.w, bh.w);
    }
}

__global__ void __launch_bounds__(NTHR, 1)
lstm_persist(const float* __restrict__ W0, const float* __restrict__ b0,
             const float* __restrict__ W1, const float* __restrict__ b1,
             const float* __restrict__ Wfc, const float* __restrict__ bfc,
             float* __restrict__ out) {
    extern __shared__ float smem[];
    float* sW    = smem;
    float* sRed  = smem + SMEM_W_FLOATS;
    float* sBias = sRed + SMEM_RED_FLOATS;

    const int cta  = blockIdx.x;
    const int tid  = threadIdx.x;
    const bool l0  = (cta < 64);
    const int lc   = l0 ? cta : cta - 64;
    const int n0   = lc * 8;
    const int lane = tid & 31, wrp = tid >> 5;
    const int wrp4 = wrp & 3;        // M-row warp within warp-group
    const int half = wrp >> 2;       // K-half this warp computes
    const int g    = lane >> 2, tig = lane & 3;
    const int rowa = wrp4 * 16 + g;
    const int aoff = tig * BSZ + rowa;
    const int boff = tig * 32 + g * 4;

    const int NK8    = l0 ? NK8_0 : NK8_1;
    const int KSPLIT = l0 ? (INP / 8) : (HID / 8);   // boundary between A-srcs
    const int khalf  = NK8 / 2;
    const int k8b    = half ? khalf : 0;
    const int k8e    = half ? NK8 : khalf;

    const unsigned epoch = g_flags[cta * 8];   // monotone across replays

    // ---- prologue: zero the two h buffers read before first write ----
    for (int e = cta * NTHR + tid; e < HID * BSZ; e += NC * NTHR) {
        g_h0T[1][e] = 0.f;
        g_h1T[0][e] = 0.f;
    }

    // ---- prologue: weight slice -> SMEM, interleaved for lds.128 ----
    {
        const float* W    = l0 ? W0 : W1;
        const float* bias = l0 ? b0 : b1;
        const int K = l0 ? K0 : K1;
        for (int e = tid; e < K * 32; e += NTHR) {
            int k = e >> 5, m = e & 31;
            int q = m >> 3, j = m & 7;
            float w = W[k * 2048 + q * 512 + n0 + j];
            sW[k * 32 + j * 4 + q] = __uint_as_float(f2tf32(w));
        }
        if (tid < 32) {
            int q = tid >> 3, j = tid & 7;
            sBias[tid] = bias[q * 512 + n0 + j];
        }
    }

    grid_bar(cta, tid, epoch, 1);

    // ---- cell state in registers (static lane->(n,r) map) ----
    float creg[4] = {0.f, 0.f, 0.f, 0.f};

    // ---- main pipelined loop: 513 phases ----
    unsigned gen = 2;
    for (int p = 0; p <= SEQ; ++p, ++gen) {
        const int rb = (p + 1) & 1, wb = p & 1;
        const bool active = l0 ? (p < SEQ) : (p >= 1);
        if (active) {
            float acc[4][4];
#pragma unroll
            for (int q = 0; q < 4; ++q) {
                float be = half ? 0.f : sBias[q * 8 + 2 * tig];
                float bo = half ? 0.f : sBias[q * 8 + 2 * tig + 1];
                acc[q][0] = be; acc[q][1] = bo; acc[q][2] = be; acc[q][3] = bo;
            }

            const float* aA = l0 ? (g_xT + p * (INP * BSZ)) : g_h0T[rb];
            const float* aB = l0 ? g_h0T[rb] : g_h1T[rb];
            gemm_range(acc, aA, aB, KSPLIT, k8b, k8e, sW, aoff, boff);

            // cross-warp-group reduction through SMEM
            float* red = sRed + (wrp4 * 32 + lane) * 16;
            if (half) {
#pragma unroll
                for (int q = 0; q < 4; ++q)
                    *(float4*)(red + q * 4) = *(float4*)acc[q];
            }
            __syncthreads();
            if (!half) {
#pragma unroll
                for (int q = 0; q < 4; ++q) {
                    float4 r4 = *(const float4*)(red + q * 4);
                    acc[q][0] += r4.x; acc[q][1] += r4.y;
                    acc[q][2] += r4.z; acc[q][3] += r4.w;
                }
                // LSTM cell update, c in registers
                float* hW = l0 ? g_h0T[wb] : g_h1T[wb];
#pragma unroll
                for (int pr = 0; pr < 4; ++pr) {
                    int r = rowa + ((pr & 2) ? 8 : 0);
                    int n = n0 + 2 * tig + (pr & 1);
                    float gi = acc[0][pr], gf = acc[1][pr];
                    float gg = acc[2][pr], go = acc[3][pr];
                    float cn = sigm(gf) * creg[pr] + sigm(gi) * fast_tanh(gg);
                    creg[pr] = cn;
                    float h = sigm(go) * fast_tanh(cn);
                    __stcg(&hW[n * BSZ + r], __uint_as_float(f2tf32(h)));
                }
            }
        }
        grid_bar(cta, tid, epoch, gen);
    }

    // ---- epilogue: pred = h1(511) @ Wfc + bfc ; phase 512 wrote buffer 0 ----
    if (cta == 0 && tid < BSZ) {
        const float* h = g_h1T[0];
        float s0 = 0.f, s1 = 0.f, s2 = 0.f, s3 = 0.f;
#pragma unroll 4
        for (int n = 0; n < HID; n += 4) {
            s0 += __ldcg(h + (n + 0) * BSZ + tid) * Wfc[n + 0];
            s1 += __ldcg(h + (n + 1) * BSZ + tid) * Wfc[n + 1];
            s2 += __ldcg(h + (n + 2) * BSZ + tid) * Wfc[n + 2];
            s3 += __ldcg(h + (n + 3) * BSZ + tid) * Wfc[n + 3];
        }
        out[tid] = (s0 + s1) + (s2 + s3) + bfc[0];
    }
}

// x[b][t][i] -> xT[t][i][b], rounded to tf32 once.
__global__ void xpose_kernel(const float* __restrict__ x) {
    int idx = blockIdx.x * blockDim.x + threadIdx.x;
    if (idx < BSZ * SEQ * INP) {
        int i = idx & (INP - 1);
        int t = (idx >> 6) & (SEQ - 1);
        int b = idx >> 15;
        g_xT[(t * INP + i) * BSZ + b] = __uint_as_float(f2tf32(x[idx]));
    }
}

extern "C" void kernel_launch(void* const* d_in, const int* in_sizes, int n_in,
                              void* d_out, int out_size) {
    (void)in_sizes; (void)n_in; (void)out_size;
    const float* x   = (const float*)d_in[0];
    const float* W0  = (const float*)d_in[1];
    const float* b0  = (const float*)d_in[2];
    const float* W1  = (const float*)d_in[3];
    const float* b1  = (const float*)d_in[4];
    const float* Wfc = (const float*)d_in[5];
    const float* bfc = (const float*)d_in[6];
    float* out = (float*)d_out;

    cudaFuncSetAttribute(lstm_persist,
                         cudaFuncAttributeMaxDynamicSharedMemorySize, SMEM_BYTES);

    xpose_kernel<<<(BSZ * SEQ * INP + 255) / 256, 256>>>(x);
    lstm_persist<<<NC, NTHR, SMEM_BYTES>>>(W0, b0, W1, b1, Wfc, bfc, out);
}

// round 3
// speedup vs baseline: 1.1281x; 1.1281x over previous
#include <cuda_runtime.h>
#include <cstdint>

// ---------------------------------------------------------------------------
// 2-layer LSTM, B=64, S=512, I=64, H=512, fc head on final h1.
// Persistent kernel, 128 CTAs (64/layer) x 256 threads (2 warp-groups).
// Phase p: layer0 computes t=p (p<512), layer1 computes t=p-1 (p>=1).
// Weights resident in SMEM (tf32). GEMM via mma.sync m16n8k8 tf32.
// A (activations) staged through a 5-slot cp.async ring per warp-group,
// 3 chunks (32 K-rows, 8KB) in flight -> L2 latency fully hidden.
// Warp-group 0 computes K-half 0, wg1 K-half 1; SMEM reduction.
// Cell state in registers. Decentralized flag grid barrier.
// ---------------------------------------------------------------------------

#define NC    128
#define NTHR  256
#define BSZ   64
#define HID   512
#define INP   64
#define SEQ   512
#define K0    576
#define K1    1024
#define NK8_0 (K0/8)
#define NK8_1 (K1/8)

#define CHROWS   32                    // K-rows per chunk
#define ASTRIDE  72                    // floats per K-row in SMEM (bank-clean)
#define SLOTF    (CHROWS*ASTRIDE)      // 2304 floats / slot
#define NSLOT    5
#define SMEM_W_FLOATS (1024*32)        // 32768
#define SMEM_A_OFF    (SMEM_W_FLOATS + 32)         // after bias, 16B aligned
#define SMEM_FLOATS   (SMEM_A_OFF + 2*NSLOT*SLOTF) // 55840
#define SMEM_BYTES    (SMEM_FLOATS*4)              // 223360

// persistent state (device globals: no allocation allowed)
__device__ float g_xT[SEQ*INP*BSZ];      // [t][i][b], tf32-rounded
__device__ float g_h0T[2][HID*BSZ];      // ping-pong [n][b]
__device__ float g_h1T[2][HID*BSZ];
__device__ unsigned g_flags[NC*8];       // 32B-strided, monotone across replays

__device__ __forceinline__ unsigned f2tf32(float f) {
    unsigned r;
    asm("cvt.rna.tf32.f32 %0, %1;" : "=r"(r) : "f"(f));
    return r;
}

__device__ __forceinline__ void mma8(float (&d)[4],
                                     unsigned a0, unsigned a1, unsigned a2, unsigned a3,
                                     float b0, float b1) {
    asm volatile(
        "mma.sync.aligned.m16n8k8.row.col.f32.tf32.tf32.f32 "
        "{%0,%1,%2,%3}, {%4,%5,%6,%7}, {%8,%9}, {%0,%1,%2,%3};"
        : "+f"(d[0]), "+f"(d[1]), "+f"(d[2]), "+f"(d[3])
        : "r"(a0), "r"(a1), "r"(a2), "r"(a3),
          "r"(__float_as_uint(b0)), "r"(__float_as_uint(b1)));
}

__device__ __forceinline__ float fast_tanh(float x) {
    float r;
    asm("tanh.approx.f32 %0, %1;" : "=f"(r) : "f"(x));
    return r;
}
__device__ __forceinline__ float sigm(float x) {
    return 0.5f * fast_tanh(0.5f * x) + 0.5f;
}

__device__ __forceinline__ void cpa16(uint32_t d, const float* s) {
    asm volatile("cp.async.cg.shared.global [%0], [%1], 16;" :: "r"(d), "l"(s) : "memory");
}
#define CP_COMMIT() asm volatile("cp.async.commit_group;" ::: "memory")
#define CP_WAIT3()  asm volatile("cp.async.wait_group 3;" ::: "memory")
#define BAR_WG(id)  asm volatile("bar.sync %0, 128;" :: "r"(id) : "memory")

// decentralized grid barrier (monotone generations survive graph replays)
__device__ __forceinline__ void grid_bar(int cta, int tid, unsigned epoch, unsigned gen) {
    __syncthreads();
    if (tid == 0) {
        __threadfence();
        *(volatile unsigned*)&g_flags[cta * 8] = epoch + gen;
    }
    if (tid < NC) {
        const unsigned target = epoch + gen;
        volatile unsigned* f = &g_flags[tid * 8];
        while ((int)(*f - target) < 0) __nanosleep(32);
    }
    __threadfence();
    __syncthreads();
}

// issue one 32-row chunk (this thread's 64B share) via cp.async
__device__ __forceinline__ void issue_chunk(int row0, const float* __restrict__ aA,
                                            const float* __restrict__ aB, int splitRows,
                                            uint32_t dstAdr, int ldr, int ldc) {
    const float* src = (row0 < splitRows) ? (aA + row0 * 64)
                                          : (aB + (row0 - splitRows) * 64);
    const float* s = src + ldr * 64 + ldc;
    cpa16(dstAdr,      s);
    cpa16(dstAdr + 16, s + 4);
    cpa16(dstAdr + 32, s + 8);
    cpa16(dstAdr + 48, s + 12);
}

__global__ void __launch_bounds__(NTHR, 1)
lstm_persist(const float* __restrict__ W0, const float* __restrict__ b0,
             const float* __restrict__ W1, const float* __restrict__ b1,
             const float* __restrict__ Wfc, const float* __restrict__ bfc,
             float* __restrict__ out) {
    extern __shared__ float smem[];
    float* sW    = smem;
    float* sBias = smem + SMEM_W_FLOATS;
    float* sA    = smem + SMEM_A_OFF;
    // reduction buffer aliases wg1's ring slot 4 (free at reduction time)
    float* sRed  = sA + (1 * NSLOT + 4) * SLOTF;

    const int cta  = blockIdx.x;
    const int tid  = threadIdx.x;
    const bool l0  = (cta < 64);
    const int lc   = l0 ? cta : cta - 64;
    const int n0   = lc * 8;
    const int lane = tid & 31, wrp = tid >> 5;
    const int wrp4 = wrp & 3;        // M-row warp within warp-group
    const int half = wrp >> 2;       // K-half this warp-group computes
    const int g    = lane >> 2, tig = lane & 3;
    const int rowa = wrp4 * 16 + g;
    const int boff = tig * 32 + g * 4;

    const int tid7 = tid & 127;           // wg-local thread id
    const int ldr  = tid7 >> 2;           // chunk row this thread loads
    const int ldc  = (tid7 & 3) * 16;     // float column base (4x float4)

    const int NK8      = l0 ? NK8_0 : NK8_1;
    const int NCH      = l0 ? 9 : 16;          // chunks per K-half
    const int splitRows = l0 ? INP : HID;       // A-source boundary (rows)
    const int halfRows  = l0 ? (K0/2) : (K1/2);
    const int rowHalf0  = half * halfRows;
    const int k8half0   = half * (NK8 / 2);

    const uint32_t saWg = (uint32_t)__cvta_generic_to_shared(sA) + half * (NSLOT * SLOTF * 4)
                        + (ldr * ASTRIDE + ldc) * 4;
    float* sAwg = sA + half * (NSLOT * SLOTF);

    const unsigned epoch = g_flags[cta * 8];

    // ---- prologue: zero h buffers read before first write ----
    for (int e = cta * NTHR + tid; e < HID * BSZ; e += NC * NTHR) {
        g_h0T[1][e] = 0.f;
        g_h1T[0][e] = 0.f;
    }

    // ---- prologue: weight slice -> SMEM (tf32), interleaved for lds.128 ----
    {
        const float* W    = l0 ? W0 : W1;
        const float* bias = l0 ? b0 : b1;
        const int K = l0 ? K0 : K1;
        for (int e = tid; e < K * 32; e += NTHR) {
            int k = e >> 5, m = e & 31;
            int q = m >> 3, j = m & 7;
            float w = W[k * 2048 + q * 512 + n0 + j];
            sW[k * 32 + j * 4 + q] = __uint_as_float(f2tf32(w));
        }
        if (tid < 32) {
            int q = tid >> 3, j = tid & 7;
            sBias[tid] = bias[q * 512 + n0 + j];
        }
    }

    grid_bar(cta, tid, epoch, 1);

    float creg[4] = {0.f, 0.f, 0.f, 0.f};

    // ---- main pipelined loop: 513 phases ----
    unsigned gen = 2;
    for (int p = 0; p <= SEQ; ++p, ++gen) {
        const int rb = (p + 1) & 1, wb = p & 1;
        const bool active = l0 ? (p < SEQ) : (p >= 1);
        if (active) {
            const float* aA = l0 ? (g_xT + p * (INP * BSZ)) : g_h0T[rb];
            const float* aB = l0 ? g_h0T[rb] : g_h1T[rb];

            // ring prologue: 3 chunks in flight (groups 0,1,2 = chunks 0,1,2)
#pragma unroll
            for (int k = 0; k < 3; ++k) {
                issue_chunk(rowHalf0 + k * CHROWS, aA, aB, splitRows,
                            saWg + (k % NSLOT) * (SLOTF * 4), ldr, ldc);
                CP_COMMIT();
            }

            float acc[4][4];
#pragma unroll
            for (int q = 0; q < 4; ++q) {
                float be = half ? 0.f : sBias[q * 8 + 2 * tig];
                float bo = half ? 0.f : sBias[q * 8 + 2 * tig + 1];
                acc[q][0] = be; acc[q][1] = bo; acc[q][2] = be; acc[q][3] = bo;
            }

            for (int c = 0; c < NCH; ++c) {
                // keep group index == chunk index: always commit exactly once
                if (c + 3 < NCH)
                    issue_chunk(rowHalf0 + (c + 3) * CHROWS, aA, aB, splitRows,
                                saWg + ((c + 3) % NSLOT) * (SLOTF * 4), ldr, ldc);
                CP_COMMIT();
                CP_WAIT3();          // chunk c complete (groups <= c drained)
                BAR_WG(1 + half);    // visible to whole warp-group

                const float* As = sAwg + (c % NSLOT) * SLOTF;
                const int k8b = k8half0 + c * 4;
#pragma unroll
                for (int k8l = 0; k8l < 4; ++k8l) {
                    const float* ap = As + (k8l * 8 + tig) * ASTRIDE + rowa;
                    unsigned a0 = __float_as_uint(ap[0]);
                    unsigned a1 = __float_as_uint(ap[8]);
                    unsigned a2 = __float_as_uint(ap[4 * ASTRIDE]);
                    unsigned a3 = __float_as_uint(ap[4 * ASTRIDE + 8]);
                    const float* bp = sW + (k8b + k8l) * 256 + boff;
                    float4 bl = *(const float4*)bp;
                    float4 bh = *(const float4*)(bp + 128);
                    mma8(acc[0], a0, a1, a2, a3, bl.x, bh.x);
                    mma8(acc[1], a0, a1, a2, a3, bl.y, bh.y);
                    mma8(acc[2], a0, a1, a2, a3, bl.z, bh.z);
                    mma8(acc[3], a0, a1, a2, a3, bl.w, bh.w);
                }
            }

            // cross-warp-group reduction through SMEM (aliases wg1 slot 4)
            float* red = sRed + (wrp4 * 32 + lane) * 16;
            if (half) {
#pragma unroll
                for (int q = 0; q < 4; ++q)
                    *(float4*)(red + q * 4) = *(float4*)acc[q];
            }
            __syncthreads();
            if (!half) {
#pragma unroll
                for (int q = 0; q < 4; ++q) {
                    float4 r4 = *(const float4*)(red + q * 4);
                    acc[q][0] += r4.x; acc[q][1] += r4.y;
                    acc[q][2] += r4.z; acc[q][3] += r4.w;
                }
                float* hW = l0 ? g_h0T[wb] : g_h1T[wb];
#pragma unroll
                for (int pr = 0; pr < 4; ++pr) {
                    int r = rowa + ((pr & 2) ? 8 : 0);
                    int n = n0 + 2 * tig + (pr & 1);
                    float gi = acc[0][pr], gf = acc[1][pr];
                    float gg = acc[2][pr], go = acc[3][pr];
                    float cn = sigm(gf) * creg[pr] + sigm(gi) * fast_tanh(gg);
                    creg[pr] = cn;
                    float h = sigm(go) * fast_tanh(cn);
                    __stcg(&hW[n * BSZ + r], __uint_as_float(f2tf32(h)));
                }
            }
        }
        grid_bar(cta, tid, epoch, gen);
    }

    // ---- epilogue: pred = h1(511) @ Wfc + bfc ; phase 512 wrote buffer 0 ----
    if (cta == 0 && tid < BSZ) {
        const float* h = g_h1T[0];
        float s0 = 0.f, s1 = 0.f, s2 = 0.f, s3 = 0.f;
#pragma unroll 4
        for (int n = 0; n < HID; n += 4) {
            s0 += __ldcg(h + (n + 0) * BSZ + tid) * Wfc[n + 0];
            s1 += __ldcg(h + (n + 1) * BSZ + tid) * Wfc[n + 1];
            s2 += __ldcg(h + (n + 2) * BSZ + tid) * Wfc[n + 2];
            s3 += __ldcg(h + (n + 3) * BSZ + tid) * Wfc[n + 3];
        }
        out[tid] = (s0 + s1) + (s2 + s3) + bfc[0];
    }
}

// x[b][t][i] -> xT[t][i][b], rounded to tf32 once.
__global__ void xpose_kernel(const float* __restrict__ x) {
    int idx = blockIdx.x * blockDim.x + threadIdx.x;
    if (idx < BSZ * SEQ * INP) {
        int i = idx & (INP - 1);
        int t = (idx >> 6) & (SEQ - 1);
        int b = idx >> 15;
        g_xT[(t * INP + i) * BSZ + b] = __uint_as_float(f2tf32(x[idx]));
    }
}

extern "C" void kernel_launch(void* const* d_in, const int* in_sizes, int n_in,
                              void* d_out, int out_size) {
    (void)in_sizes; (void)n_in; (void)out_size;
    const float* x   = (const float*)d_in[0];
    const float* W0  = (const float*)d_in[1];
    const float* b0  = (const float*)d_in[2];
    const float* W1  = (const float*)d_in[3];
    const float* b1  = (const float*)d_in[4];
    const float* Wfc = (const float*)d_in[5];
    const float* bfc = (const float*)d_in[6];
    float* out = (float*)d_out;

    cudaFuncSetAttribute(lstm_persist,
                         cudaFuncAttributeMaxDynamicSharedMemorySize, SMEM_BYTES);

    xpose_kernel<<<(BSZ * SEQ * INP + 255) / 256, 256>>>(x);
    lstm_persist<<<NC, NTHR, SMEM_BYTES>>>(W0, b0, W1, b1, Wfc, bfc, out);
}

// round 4
// speedup vs baseline: 1.7495x; 1.5509x over previous
#include <cuda_runtime.h>
#include <cuda_bf16.h>
#include <cstdint>

// ---------------------------------------------------------------------------
// 2-layer LSTM, B=64, S=512, I=64, H=512, fc head on final h1.
// 64 persistent CTAs x 256 threads. Each CTA owns a 32-gate-column slice of
// BOTH layers: warp-group 0 = layer 0, warp-group 1 = layer 1 (full K each,
// no split-K reduction). Phase p: wg0 computes t=p (p<512), wg1 t=p-1.
// bf16 mma.m16n8k16, fp32 accumulate. Weights + A-ring in SMEM.
// Activations stored as bf16x2 pair-words [k/2][b]. cp.async .cg staging.
// Cell state in registers. Packed-flag grid barrier, monotone generations.
// ---------------------------------------------------------------------------

#define NC    64
#define NTHR  256
#define BSZ   64
#define SEQ   512

#define AROWW 64                      // words per kp-row in gmem (b dim)
#define ASTR  72                      // padded words per kp-row in SMEM
#define CHKP  32                      // kp-rows per chunk
#define SLOTW (CHKP*ASTR)             // 2304 words per slot
#define NSLOT 4
#define WSTR  40                      // sW padded words per kp-row

#define KP0   288                     // layer0 K/2 (576/2)
#define KP1   512                     // layer1 K/2
#define NCH0  9                       // KP0/CHKP
#define NCH1  16

#define SW0_OFF   0
#define SW1_OFF   (KP0*WSTR)                  // 11520
#define SBIAS_OFF (SW1_OFF + KP1*WSTR)        // 32000
#define SA_OFF    (SBIAS_OFF + 64)            // 32064
#define SMEM_WORDS (SA_OFF + 2*NSLOT*SLOTW)   // 50496
#define SMEM_BYTES (SMEM_WORDS*4)             // 201984

// persistent state (device globals; allocation is forbidden)
__device__ uint32_t g_xw[SEQ*32*BSZ];     // [t][kp<32][b] bf16x2 (k even lo)
__device__ uint32_t g_h0w[2][256*BSZ];    // ping-pong [kp][b]
__device__ uint32_t g_h1w[2][256*BSZ];
__device__ unsigned g_flags[64];          // packed, monotone across replays

__device__ __forceinline__ uint32_t packbf2(float lo, float hi) {
    uint32_t r;
    asm("cvt.rn.bf16x2.f32 %0, %1, %2;" : "=r"(r) : "f"(hi), "f"(lo));
    return r;
}

__device__ __forceinline__ void mma16(float (&d)[4],
                                      uint32_t a0, uint32_t a1, uint32_t a2, uint32_t a3,
                                      uint32_t b0, uint32_t b1) {
    asm volatile(
        "mma.sync.aligned.m16n8k16.row.col.f32.bf16.bf16.f32 "
        "{%0,%1,%2,%3}, {%4,%5,%6,%7}, {%8,%9}, {%0,%1,%2,%3};"
        : "+f"(d[0]), "+f"(d[1]), "+f"(d[2]), "+f"(d[3])
        : "r"(a0), "r"(a1), "r"(a2), "r"(a3), "r"(b0), "r"(b1));
}

__device__ __forceinline__ float fast_tanh(float x) {
    float r;
    asm("tanh.approx.f32 %0, %1;" : "=f"(r) : "f"(x));
    return r;
}
__device__ __forceinline__ float sigm(float x) {
    return 0.5f * fast_tanh(0.5f * x) + 0.5f;
}

__device__ __forceinline__ void cpa16(uint32_t d, const uint32_t* s) {
    asm volatile("cp.async.cg.shared.global [%0], [%1], 16;" :: "r"(d), "l"(s) : "memory");
}
#define CP_COMMIT() asm volatile("cp.async.commit_group;" ::: "memory")
#define CP_WAIT3()  asm volatile("cp.async.wait_group 3;" ::: "memory")
#define BAR_WG(id)  asm volatile("bar.sync %0, 128;" :: "r"(id) : "memory")

// grid barrier: packed flags, monotone generations (replay-safe)
__device__ __forceinline__ void grid_bar(int cta, int tid, unsigned target) {
    __syncthreads();
    if (tid == 0) {
        __threadfence();
        *(volatile unsigned*)&g_flags[cta] = target;
    }
    if (tid < NC) {
        volatile unsigned* f = &g_flags[tid];
        while ((int)(*f - target) < 0) __nanosleep(20);
    }
    __threadfence();
    __syncthreads();
}

// stage one 32-kp chunk: this thread's 64B share via 4x cp.async.16
__device__ __forceinline__ void issue_chunk(const uint32_t* __restrict__ src,
                                            uint32_t dstAdr) {
    cpa16(dstAdr,      src);
    cpa16(dstAdr + 16, src + 4);
    cpa16(dstAdr + 32, src + 8);
    cpa16(dstAdr + 48, src + 12);
}

__global__ void __launch_bounds__(NTHR, 1)
lstm_persist(const float* __restrict__ W0, const float* __restrict__ b0,
             const float* __restrict__ W1, const float* __restrict__ b1,
             const float* __restrict__ Wfc, const float* __restrict__ bfc,
             float* __restrict__ out) {
    extern __shared__ uint32_t sm[];
    float* sBias = (float*)(sm + SBIAS_OFF);

    const int cta  = blockIdx.x;
    const int tid  = threadIdx.x;
    const int n0   = cta * 8;                  // h-column base of this CTA
    const int lane = tid & 31, wrp = tid >> 5;
    const int wrp4 = wrp & 3;                  // M-warp within warp-group
    const int wl   = wrp >> 2;                 // 0 = layer0, 1 = layer1
    const int g    = lane >> 2, t4 = lane & 3;
    const int rowa = wrp4 * 16 + g;            // batch row for d0

    const int tid7 = tid & 127;
    const int ldr  = tid7 >> 2;                // kp-row this thread stages
    const int ldc  = (tid7 & 3) * 16;          // word col (4x16B)

    const int NCH    = wl ? NCH1 : NCH0;
    const int splitC = wl ? 8 : 1;             // chunks from source A vs B
    const uint32_t* sWl = sm + (wl ? SW1_OFF : SW0_OFF);
    const int biasOff = wl * 32;

    const uint32_t saWgAdr = (uint32_t)__cvta_generic_to_shared(sm)
                           + (SA_OFF + wl * NSLOT * SLOTW) * 4
                           + (ldr * ASTR + ldc) * 4;
    const uint32_t* sAwg = sm + SA_OFF + wl * NSLOT * SLOTW;

    const unsigned epoch = g_flags[cta];

    // ---- prologue: zero h buffers that are read before first write ----
    for (int e = cta * NTHR + tid; e < 256 * BSZ; e += NC * NTHR) {
        g_h0w[1][e] = 0u;
        g_h1w[0][e] = 0u;
    }

    // ---- prologue: weights -> SMEM as bf16x2, layout [kp][q*8+j] ----
    {
        // layer0
        for (int e = tid; e < KP0 * 32; e += NTHR) {
            int kp = e >> 5, c = e & 31;
            int q = c >> 3, j = c & 7;
            const float* w = W0 + (2 * kp) * 2048 + q * 512 + n0 + j;
            sm[SW0_OFF + kp * WSTR + c] = packbf2(w[0], w[2048]);
        }
        // layer1
        for (int e = tid; e < KP1 * 32; e += NTHR) {
            int kp = e >> 5, c = e & 31;
            int q = c >> 3, j = c & 7;
            const float* w = W1 + (2 * kp) * 2048 + q * 512 + n0 + j;
            sm[SW1_OFF + kp * WSTR + c] = packbf2(w[0], w[2048]);
        }
        if (tid < 64) {
            int l = tid >> 5, c = tid & 31;
            int q = c >> 3, j = c & 7;
            sBias[tid] = (l ? b1 : b0)[q * 512 + n0 + j];
        }
    }

    grid_bar(cta, tid, epoch + 1);

    float creg[4] = {0.f, 0.f, 0.f, 0.f};

    // ---- main loop: 513 phases ----
    for (int p = 0; p <= SEQ; ++p) {
        const int rb = (p + 1) & 1, wb = p & 1;
        const bool active = wl ? (p >= 1) : (p < SEQ);
        if (active) {
            // chunk sources: wg0: [x_t | h0(p-1)], wg1: [h0(p-1) | h1(p-2)]
            const uint32_t* pA = wl ? g_h0w[rb] : (g_xw + p * (32 * BSZ));
            const uint32_t* pB = wl ? g_h1w[rb] : g_h0w[rb];
            const uint32_t* thrOff0 = pA + ldr * AROWW + ldc;
            const uint32_t* thrOff1 = pB + ldr * AROWW + ldc;

#pragma unroll
            for (int k = 0; k < 3; ++k) {
                const uint32_t* src = (k < splitC)
                    ? thrOff0 + k * (CHKP * AROWW)
                    : thrOff1 + (k - splitC) * (CHKP * AROWW);
                issue_chunk(src, saWgAdr + (k & 3) * (SLOTW * 4));
                CP_COMMIT();
            }

            float acc[4][4];
#pragma unroll
            for (int q = 0; q < 4; ++q) {
                float be = sBias[biasOff + q * 8 + 2 * t4];
                float bo = sBias[biasOff + q * 8 + 2 * t4 + 1];
                acc[q][0] = be; acc[q][1] = bo; acc[q][2] = be; acc[q][3] = bo;
            }

            for (int c = 0; c < NCH; ++c) {
                int cn = c + 3;
                if (cn < NCH) {
                    const uint32_t* src = (cn < splitC)
                        ? thrOff0 + cn * (CHKP * AROWW)
                        : thrOff1 + (cn - splitC) * (CHKP * AROWW);
                    issue_chunk(src, saWgAdr + (cn & 3) * (SLOTW * 4));
                }
                CP_COMMIT();            // group index == chunk index
                CP_WAIT3();             // chunk c resident
                BAR_WG(1 + wl);

                const uint32_t* As = sAwg + (c & 3) * SLOTW;
                const uint32_t* Bs = sWl + (c * CHKP) * WSTR + g;
#pragma unroll
                for (int k16 = 0; k16 < 4; ++k16) {
                    const uint32_t* ap = As + (k16 * 8 + t4) * ASTR;
                    uint32_t a0 = ap[rowa];
                    uint32_t a1 = ap[rowa + 8];
                    uint32_t a2 = ap[4 * ASTR + rowa];
                    uint32_t a3 = ap[4 * ASTR + rowa + 8];
                    const uint32_t* bp = Bs + (k16 * 8 + t4) * WSTR;
#pragma unroll
                    for (int q = 0; q < 4; ++q)
                        mma16(acc[q], a0, a1, a2, a3,
                              bp[q * 8], bp[4 * WSTR + q * 8]);
                }
            }

            // ---- cell update (per-thread, gates resident) + packed h store
            uint32_t* hw = wl ? g_h1w[wb] : g_h0w[wb];
            float hv[4];
#pragma unroll
            for (int pr = 0; pr < 4; ++pr) {
                float gi = acc[0][pr], gf = acc[1][pr];
                float gg = acc[2][pr], go = acc[3][pr];
                float cn2 = sigm(gf) * creg[pr] + sigm(gi) * fast_tanh(gg);
                creg[pr] = cn2;
                hv[pr] = sigm(go) * fast_tanh(cn2);
            }
            // pr0:(rowa, n even) pr1:(rowa, odd) pr2:(rowa+8, even) pr3:(+8, odd)
            const int kpIdx = cta * 4 + t4;     // (n0 + 2*t4)/2
            __stcg(&hw[kpIdx * BSZ + rowa],     packbf2(hv[0], hv[1]));
            __stcg(&hw[kpIdx * BSZ + rowa + 8], packbf2(hv[2], hv[3]));
        }
        grid_bar(cta, tid, epoch + 2 + p);
    }

    // ---- epilogue: pred = h1(511) @ Wfc + bfc; phase 512 wrote h1w[0] ----
    if (cta == 0 && tid < BSZ) {
        const uint32_t* h = g_h1w[0];
        float s0 = 0.f, s1 = 0.f;
#pragma unroll 4
        for (int kp = 0; kp < 256; ++kp) {
            uint32_t w = __ldcg(&h[kp * BSZ + tid]);
            float lo = __bfloat162float(__ushort_as_bfloat16((unsigned short)(w & 0xFFFF)));
            float hi = __bfloat162float(__ushort_as_bfloat16((unsigned short)(w >> 16)));
            s0 += lo * Wfc[2 * kp];
            s1 += hi * Wfc[2 * kp + 1];
        }
        out[tid] = s0 + s1 + bfc[0];
    }
}

// x[b][t][i] -> pair-words [t][kp][b] (bf16x2, even k in low half)
__global__ void xpose_kernel(const float* __restrict__ x) {
    int idx = blockIdx.x * blockDim.x + threadIdx.x;
    if (idx < SEQ * 32 * BSZ) {
        int b  = idx & 63;
        int kp = (idx >> 6) & 31;
        int t  = idx >> 11;
        const float* xe = x + ((b * SEQ) + t) * 64 + 2 * kp;
        g_xw[idx] = packbf2(xe[0], xe[1]);
    }
}

extern "C" void kernel_launch(void* const* d_in, const int* in_sizes, int n_in,
                              void* d_out, int out_size) {
    (void)in_sizes; (void)n_in; (void)out_size;
    const float* x   = (const float*)d_in[0];
    const float* W0  = (const float*)d_in[1];
    const float* b0  = (const float*)d_in[2];
    const float* W1  = (const float*)d_in[3];
    const float* b1  = (const float*)d_in[4];
    const float* Wfc = (const float*)d_in[5];
    const float* bfc = (const float*)d_in[6];
    float* out = (float*)d_out;

    cudaFuncSetAttribute(lstm_persist,
                         cudaFuncAttributeMaxDynamicSharedMemorySize, SMEM_BYTES);

    xpose_kernel<<<(SEQ * 32 * BSZ + 255) / 256, 256>>>(x);
    lstm_persist<<<NC, NTHR, SMEM_BYTES>>>(W0, b0, W1, b1, Wfc, bfc, out);
}

// round 5
// speedup vs baseline: 2.2278x; 1.2734x over previous
#include <cuda_runtime.h>
#include <cuda_bf16.h>
#include <cstdint>

// ---------------------------------------------------------------------------
// 2-layer LSTM, B=64, S=512, I=64, H=512, fc head on final h1.
// 64 persistent CTAs x 256 threads. wg0 = layer0 (K=576, 9 chunks),
// wg1 = layer1 (K=1024, 16 chunks). NO grid barrier: producer flags
// g_f0/g_f1 + dataflow waits. h ring-buffered 4 deep so wg0 runs ahead;
// wg1 overlaps its peer-sync with the h0 half of its GEMM.
// bf16 mma.m16n8k16, fp32 accumulate, weights + A-ring in SMEM.
// ---------------------------------------------------------------------------

#define NC    64
#define NTHR  256
#define BSZ   64
#define SEQ   512

#define AROWW 64                      // words per kp-row in gmem (b dim)
#define ASTR  72                      // padded words per kp-row in SMEM
#define CHKP  32                      // kp-rows per chunk
#define SLOTW (CHKP*ASTR)             // 2304 words per slot
#define NSLOT 4
#define WSTR  40                      // sW padded words per kp-row

#define KP0   288                     // layer0 K/2
#define KP1   512                     // layer1 K/2
#define NCH0  9
#define NCH1  16

#define SW0_OFF   0
#define SW1_OFF   (KP0*WSTR)
#define SBIAS_OFF (SW1_OFF + KP1*WSTR)
#define SA_OFF    (SBIAS_OFF + 64)
#define SMEM_WORDS (SA_OFF + 2*NSLOT*SLOTW)
#define SMEM_BYTES (SMEM_WORDS*4)             // 201984

// persistent state (device globals; allocation forbidden)
__device__ uint32_t g_xw[SEQ*32*BSZ];     // [t][kp<32][b] bf16x2
__device__ uint32_t g_h0w[4][256*BSZ];    // 4-deep ring [kp][b]
__device__ uint32_t g_h1w[4][256*BSZ];
__device__ unsigned g_f0[64];             // wg0 producer flags, monotone
__device__ unsigned g_f1[64];             // wg1 producer flags, monotone

__device__ __forceinline__ uint32_t packbf2(float lo, float hi) {
    uint32_t r;
    asm("cvt.rn.bf16x2.f32 %0, %1, %2;" : "=r"(r) : "f"(hi), "f"(lo));
    return r;
}

__device__ __forceinline__ void mma16(float (&d)[4],
                                      uint32_t a0, uint32_t a1, uint32_t a2, uint32_t a3,
                                      uint32_t b0, uint32_t b1) {
    asm volatile(
        "mma.sync.aligned.m16n8k16.row.col.f32.bf16.bf16.f32 "
        "{%0,%1,%2,%3}, {%4,%5,%6,%7}, {%8,%9}, {%0,%1,%2,%3};"
        : "+f"(d[0]), "+f"(d[1]), "+f"(d[2]), "+f"(d[3])
        : "r"(a0), "r"(a1), "r"(a2), "r"(a3), "r"(b0), "r"(b1));
}

__device__ __forceinline__ float fast_tanh(float x) {
    float r;
    asm("tanh.approx.f32 %0, %1;" : "=f"(r) : "f"(x));
    return r;
}
__device__ __forceinline__ float sigm(float x) {
    return 0.5f * fast_tanh(0.5f * x) + 0.5f;
}

__device__ __forceinline__ void cpa16(uint32_t d, const uint32_t* s) {
    asm volatile("cp.async.cg.shared.global [%0], [%1], 16;" :: "r"(d), "l"(s) : "memory");
}
#define CP_COMMIT() asm volatile("cp.async.commit_group;" ::: "memory")
#define CP_WAIT3()  asm volatile("cp.async.wait_group 3;" ::: "memory")
#define BAR_WG(id)  asm volatile("bar.sync %0, 128;" :: "r"(id) : "memory")

// warp-group wait: 64 pollers, then wg-wide named barrier
__device__ __forceinline__ void wg_wait(volatile unsigned* flags, unsigned target,
                                        int tid7, int barid) {
    if (tid7 < 64) {
        volatile unsigned* f = &flags[tid7];
        while ((int)(*f - target) < 0) __nanosleep(20);
    }
    BAR_WG(barid);
}

// warp-group post: wg stores done -> fence -> flag
__device__ __forceinline__ void wg_post(unsigned* flag, unsigned val,
                                        int tid7, int barid) {
    BAR_WG(barid);
    if (tid7 == 0) {
        __threadfence();
        *(volatile unsigned*)flag = val;
    }
}

__device__ __forceinline__ void issue_chunk(const uint32_t* __restrict__ src,
                                            uint32_t dstAdr) {
    cpa16(dstAdr,      src);
    cpa16(dstAdr + 16, src + 4);
    cpa16(dstAdr + 32, src + 8);
    cpa16(dstAdr + 48, src + 12);
}

__global__ void __launch_bounds__(NTHR, 1)
lstm_persist(const float* __restrict__ W0, const float* __restrict__ b0,
             const float* __restrict__ W1, const float* __restrict__ b1,
             const float* __restrict__ Wfc, const float* __restrict__ bfc,
             float* __restrict__ out) {
    extern __shared__ uint32_t sm[];
    float* sBias = (float*)(sm + SBIAS_OFF);

    const int cta  = blockIdx.x;
    const int tid  = threadIdx.x;
    const int n0   = cta * 8;
    const int lane = tid & 31, wrp = tid >> 5;
    const int wrp4 = wrp & 3;
    const int wl   = wrp >> 2;                 // 0 = layer0, 1 = layer1
    const int g    = lane >> 2, t4 = lane & 3;
    const int rowa = wrp4 * 16 + g;

    const int tid7 = tid & 127;
    const int ldr  = tid7 >> 2;
    const int ldc  = (tid7 & 3) * 16;
    const int thrOff = ldr * AROWW + ldc;

    const int barid = 1 + wl;
    const uint32_t saWgAdr = (uint32_t)__cvta_generic_to_shared(sm)
                           + (SA_OFF + wl * NSLOT * SLOTW) * 4
                           + (ldr * ASTR + ldc) * 4;
    const uint32_t* sAwg = sm + SA_OFF + wl * NSLOT * SLOTW;
    const uint32_t* sWl  = sm + (wl ? SW1_OFF : SW0_OFF);
    const int biasOff = wl * 32;
    const int kpIdx = cta * 4 + t4;

    const unsigned base = g_f0[cta];   // == g_f1[cta] at entry, monotone

    // ---- prologue: zero slot-3 h rings (h(-1) reads) ----
    for (int e = cta * NTHR + tid; e < 256 * BSZ; e += NC * NTHR) {
        g_h0w[3][e] = 0u;
        g_h1w[3][e] = 0u;
    }

    // ---- prologue: weights -> SMEM as bf16x2 ----
    for (int e = tid; e < KP0 * 32; e += NTHR) {
        int kp = e >> 5, c = e & 31;
        int q = c >> 3, j = c & 7;
        const float* w = W0 + (2 * kp) * 2048 + q * 512 + n0 + j;
        sm[SW0_OFF + kp * WSTR + c] = packbf2(w[0], w[2048]);
    }
    for (int e = tid; e < KP1 * 32; e += NTHR) {
        int kp = e >> 5, c = e & 31;
        int q = c >> 3, j = c & 7;
        const float* w = W1 + (2 * kp) * 2048 + q * 512 + n0 + j;
        sm[SW1_OFF + kp * WSTR + c] = packbf2(w[0], w[2048]);
    }
    if (tid < 64) {
        int l = tid >> 5, c = tid & 31;
        int q = c >> 3, j = c & 7;
        sBias[tid] = (l ? b1 : b0)[q * 512 + n0 + j];
    }

    __syncthreads();
    if (tid == 0) {                    // publish init (zeros visible)
        __threadfence();
        *(volatile unsigned*)&g_f0[cta] = base + 1;
    }

    float creg[4] = {0.f, 0.f, 0.f, 0.f};
    float accb[4][2];
#pragma unroll
    for (int q = 0; q < 4; ++q) {
        accb[q][0] = sBias[biasOff + q * 8 + 2 * t4];
        accb[q][1] = sBias[biasOff + q * 8 + 2 * t4 + 1];
    }

    if (wl == 0) {
        // =============== layer 0: phases p = 0..511, computes t=p ===========
        for (int p = 0; p < SEQ; ++p) {
            const uint32_t* pX = g_xw + p * (32 * BSZ) + thrOff;
            const uint32_t* pH = g_h0w[(p + 3) & 3] + thrOff;   // h0(p-1)

            issue_chunk(pX, saWgAdr);                  // chunk 0 = x (indep)
            CP_COMMIT();
            wg_wait(g_f0, base + 1 + p, tid7, barid);  // h0(p-1) ready
            if (p >= 2)
                wg_wait(g_f1, base + p - 1, tid7, barid);  // ring back-pressure
            issue_chunk(pH,                    saWgAdr + 1 * (SLOTW * 4)); CP_COMMIT();
            issue_chunk(pH + 1 * (CHKP*AROWW), saWgAdr + 2 * (SLOTW * 4)); CP_COMMIT();

            float acc[4][4];
#pragma unroll
            for (int q = 0; q < 4; ++q) {
                acc[q][0] = accb[q][0]; acc[q][1] = accb[q][1];
                acc[q][2] = accb[q][0]; acc[q][3] = accb[q][1];
            }

            for (int c = 0; c < NCH0; ++c) {
                int cn = c + 3;
                if (cn < NCH0)
                    issue_chunk(pH + (cn - 1) * (CHKP * AROWW),
                                saWgAdr + (cn & 3) * (SLOTW * 4));
                CP_COMMIT();
                CP_WAIT3();
                BAR_WG(barid);
                const uint32_t* As = sAwg + (c & 3) * SLOTW;
                const uint32_t* Bs = sWl + (c * CHKP) * WSTR + g;
#pragma unroll
                for (int k16 = 0; k16 < 4; ++k16) {
                    const uint32_t* ap = As + (k16 * 8 + t4) * ASTR;
                    uint32_t a0 = ap[rowa];
                    uint32_t a1 = ap[rowa + 8];
                    uint32_t a2 = ap[4 * ASTR + rowa];
                    uint32_t a3 = ap[4 * ASTR + rowa + 8];
                    const uint32_t* bp = Bs + (k16 * 8 + t4) * WSTR;
#pragma unroll
                    for (int q = 0; q < 4; ++q)
                        mma16(acc[q], a0, a1, a2, a3, bp[q * 8], bp[4 * WSTR + q * 8]);
                }
            }

            uint32_t* hw = g_h0w[p & 3];
            float hv[4];
#pragma unroll
            for (int pr = 0; pr < 4; ++pr) {
                float cn2 = sigm(acc[1][pr]) * creg[pr]
                          + sigm(acc[0][pr]) * fast_tanh(acc[2][pr]);
                creg[pr] = cn2;
                hv[pr] = sigm(acc[3][pr]) * fast_tanh(cn2);
            }
            __stcg(&hw[kpIdx * BSZ + rowa],     packbf2(hv[0], hv[1]));
            __stcg(&hw[kpIdx * BSZ + rowa + 8], packbf2(hv[2], hv[3]));
            wg_post(&g_f0[cta], base + 2 + p, tid7, barid);
        }
        wg_post(&g_f0[cta], base + 2 + SEQ, tid7, barid);  // equalize flags

        // epilogue: cta0 wg0 computes fc after all wg1s finish phase 512
        if (cta == 0) {
            wg_wait(g_f1, base + 2 + SEQ, tid7, barid);
            if (tid7 < BSZ) {
                const uint32_t* h = g_h1w[(SEQ - 1) & 3];
                float s0 = 0.f, s1 = 0.f;
#pragma unroll 4
                for (int kp = 0; kp < 256; ++kp) {
                    uint32_t w = __ldcg(&h[kp * BSZ + tid7]);
                    float lo = __bfloat162float(__ushort_as_bfloat16((unsigned short)(w & 0xFFFF)));
                    float hi = __bfloat162float(__ushort_as_bfloat16((unsigned short)(w >> 16)));
                    s0 += lo * Wfc[2 * kp];
                    s1 += hi * Wfc[2 * kp + 1];
                }
                out[tid7] = s0 + s1 + bfc[0];
            }
        }
    } else {
        // =============== layer 1: phases p = 1..512, computes t=p-1 =========
        wg_post(&g_f1[cta], base + 2, tid7, barid);        // "phase 0" post
        for (int p = 1; p <= SEQ; ++p) {
            const uint32_t* pH0 = g_h0w[(p + 3) & 3] + thrOff;  // h0(p-1)
            const uint32_t* pH1 = g_h1w[(p + 2) & 3] + thrOff;  // h1(p-2)

            wg_wait(g_f0, base + 1 + p, tid7, barid);  // usually already true
            issue_chunk(pH0,                    saWgAdr);                  CP_COMMIT();
            issue_chunk(pH0 + 1 * (CHKP*AROWW), saWgAdr + 1 * (SLOTW*4)); CP_COMMIT();
            issue_chunk(pH0 + 2 * (CHKP*AROWW), saWgAdr + 2 * (SLOTW*4)); CP_COMMIT();

            float acc[4][4];
#pragma unroll
            for (int q = 0; q < 4; ++q) {
                acc[q][0] = accb[q][0]; acc[q][1] = accb[q][1];
                acc[q][2] = accb[q][0]; acc[q][3] = accb[q][1];
            }

            for (int c = 0; c < NCH1; ++c) {
                int cn = c + 3;
                if (cn < NCH1) {
                    if (cn == 8)                       // h1 part: peer sync,
                        wg_wait(g_f1, base + 1 + p, tid7, barid);  // overlapped
                    const uint32_t* src = (cn < 8)
                        ? pH0 + cn * (CHKP * AROWW)
                        : pH1 + (cn - 8) * (CHKP * AROWW);
                    issue_chunk(src, saWgAdr + (cn & 3) * (SLOTW * 4));
                }
                CP_COMMIT();
                CP_WAIT3();
                BAR_WG(barid);
                const uint32_t* As = sAwg + (c & 3) * SLOTW;
                const uint32_t* Bs = sWl + (c * CHKP) * WSTR + g;
#pragma unroll
                for (int k16 = 0; k16 < 4; ++k16) {
                    const uint32_t* ap = As + (k16 * 8 + t4) * ASTR;
                    uint32_t a0 = ap[rowa];
                    uint32_t a1 = ap[rowa + 8];
                    uint32_t a2 = ap[4 * ASTR + rowa];
                    uint32_t a3 = ap[4 * ASTR + rowa + 8];
                    const uint32_t* bp = Bs + (k16 * 8 + t4) * WSTR;
#pragma unroll
                    for (int q = 0; q < 4; ++q)
                        mma16(acc[q], a0, a1, a2, a3, bp[q * 8], bp[4 * WSTR + q * 8]);
                }
            }

            uint32_t* hw = g_h1w[(p - 1) & 3];
            float hv[4];
#pragma unroll
            for (int pr = 0; pr < 4; ++pr) {
                float cn2 = sigm(acc[1][pr]) * creg[pr]
                          + sigm(acc[0][pr]) * fast_tanh(acc[2][pr]);
                creg[pr] = cn2;
                hv[pr] = sigm(acc[3][pr]) * fast_tanh(cn2);
            }
            __stcg(&hw[kpIdx * BSZ + rowa],     packbf2(hv[0], hv[1]));
            __stcg(&hw[kpIdx * BSZ + rowa + 8], packbf2(hv[2], hv[3]));
            wg_post(&g_f1[cta], base + 2 + p, tid7, barid);
        }
    }
}

// x[b][t][i] -> pair-words [t][kp][b]
__global__ void xpose_kernel(const float* __restrict__ x) {
    int idx = blockIdx.x * blockDim.x + threadIdx.x;
    if (idx < SEQ * 32 * BSZ) {
        int b  = idx & 63;
        int kp = (idx >> 6) & 31;
        int t  = idx >> 11;
        const float* xe = x + ((b * SEQ) + t) * 64 + 2 * kp;
        g_xw[idx] = packbf2(xe[0], xe[1]);
    }
}

extern "C" void kernel_launch(void* const* d_in, const int* in_sizes, int n_in,
                              void* d_out, int out_size) {
    (void)in_sizes; (void)n_in; (void)out_size;
    const float* x   = (const float*)d_in[0];
    const float* W0  = (const float*)d_in[1];
    const float* b0  = (const float*)d_in[2];
    const float* W1  = (const float*)d_in[3];
    const float* b1  = (const float*)d_in[4];
    const float* Wfc = (const float*)d_in[5];
    const float* bfc = (const float*)d_in[6];
    float* out = (float*)d_out;

    cudaFuncSetAttribute(lstm_persist,
                         cudaFuncAttributeMaxDynamicSharedMemorySize, SMEM_BYTES);

    xpose_kernel<<<(SEQ * 32 * BSZ + 255) / 256, 256>>>(x);
    lstm_persist<<<NC, NTHR, SMEM_BYTES>>>(W0, b0, W1, b1, Wfc, bfc, out);
}